// round 3
// baseline (speedup 1.0000x reference)
#include <cuda_runtime.h>
#include <math.h>

// Problem constants
#define BB   2048                 // graphs
#define NN   64                   // nodes per graph
#define BN   (BB*NN)              // 131072 nodes
#define KSEL 52                   // top-k
#define TT   16                   // subtokens per node
#define DD   128                  // embed dim
#define D2   256                  // 2*D
#define HH   256                  // hidden
#define EPG  256                  // edges per graph
#define ETOT (BB*EPG)             // 524288 edges
#define NSTAT 512                 // stat-reduction blocks (BN/NSTAT = 256 rows each)

// ---------------- scratch (device globals; no allocation allowed) -----------
__device__ float  g_h0[BN*DD];          // 64 MB : x + agg  (GINE output pre-MLP)
__device__ float  g_h1[BN*D2];          // 128 MB: h0@W1 + b1 (pre-BN)
__device__ float  g_psum[NSTAT*D2];     // 512 KB: per-slab column sums
__device__ float  g_psumsq[NSTAT*D2];   // 512 KB
__device__ float  g_scale[D2];          // gamma * rsigma
__device__ float  g_shift[D2];          // beta - mu*gamma*rsigma
__device__ float  g_invnorm;            // 1/||topk_w||
__device__ float  g_cat[BB*2*HH];       // 4 MB : [max-pool || mean-pool]

// ============================================================================
// K1: per-graph block. subtoken-embed sum/avg + node-type embed -> x in smem;
// counting-sort edges by dst; agg = sum relu(x[src]); h0 = x + agg -> global.
// ============================================================================
__global__ __launch_bounds__(256) void k1_embed_edges(
    const int* __restrict__ tokens, const int* __restrict__ ntype,
    const int* __restrict__ eidx,
    const float* __restrict__ st, const float* __restrict__ nt)
{
    const int g = blockIdx.x;
    const int t = threadIdx.x;

    __shared__ int   s_tok[NN*TT];     // 4 KB
    __shared__ float s_inv[NN];
    __shared__ int   s_nt[NN];
    __shared__ float s_x[NN*DD];       // 32 KB
    __shared__ int   s_deg[NN];
    __shared__ int   s_start[NN+1];
    __shared__ int   s_src[EPG];

    if (t < NN) s_deg[t] = 0;
    #pragma unroll
    for (int p = 0; p < 4; p++) {
        int i = t + 256*p;
        s_tok[i] = tokens[g*(NN*TT) + i];
    }
    if (t < NN) s_nt[t] = ntype[g*NN + t];

    // edge endpoints (one edge per thread; edges stay within the graph)
    const int srcl = eidx[g*EPG + t]        - g*NN;
    const int dstl = eidx[ETOT + g*EPG + t] - g*NN;
    __syncthreads();

    // non-pad counts -> averaging factor (count==0 keeps raw sum)
    if (t < NN) {
        int c = 0;
        #pragma unroll
        for (int k = 0; k < TT; k++) c += (s_tok[t*TT + k] != 0);
        s_inv[t] = c ? (1.0f / (float)c) : 1.0f;
    }
    const int rank = atomicAdd(&s_deg[dstl], 1);
    __syncthreads();

    if (t == 0) {
        int a = 0;
        for (int n = 0; n < NN; n++) { s_start[n] = a; a += s_deg[n]; }
        s_start[NN] = a;
    }
    __syncthreads();
    s_src[s_start[dstl] + rank] = srcl;

    // x = avg(subtoken embeds) + node-type embed
    // 256 threads: dim d = t&127, two nodes per pass (n parity = t>>7)
    {
        const int d = t & 127;
        for (int n = (t >> 7); n < NN; n += 2) {
            float sum = 0.f;
            #pragma unroll
            for (int k = 0; k < TT; k++)
                sum += st[s_tok[n*TT + k]*DD + d];
            s_x[n*DD + d] = sum * s_inv[n] + nt[s_nt[n]*DD + d];
        }
    }
    __syncthreads();

    // aggregation: thread owns node n = t>>2, dim quarter q = t&3 (32 dims),
    // lane-staggered dim index -> conflict-free smem banks.
    const int n    = t >> 2;
    const int d0   = (t & 3) * 32;
    const int lane = t & 31;
    float acc[32];
    #pragma unroll
    for (int j = 0; j < 32; j++) acc[j] = 0.f;

    const int e0 = s_start[n], e1 = s_start[n+1];
    for (int e = e0; e < e1; e++) {
        const int s = s_src[e];
        #pragma unroll
        for (int j = 0; j < 32; j++) {
            const int dd = d0 + ((j + lane) & 31);
            acc[j] += fmaxf(s_x[s*DD + dd], 0.f);
        }
    }
    __syncthreads();   // all relu reads of s_x complete

    #pragma unroll
    for (int j = 0; j < 32; j++) {
        const int dd = d0 + ((j + lane) & 31);
        s_x[n*DD + dd] += acc[j];          // h0 = x + agg, unique (n,dd) owner
    }
    __syncthreads();

    // coalesced write-out
    #pragma unroll
    for (int p = 0; p < 32; p++) {
        const int i = t + 256*p;
        g_h0[g*(NN*DD) + i] = s_x[i];
    }
}

// ============================================================================
// K2: GEMM1  h1 = h0 @ W1 + b1.   Tile 64 rows x 256 cols, K=128 in 32-chunks.
// 256 threads, thread tile 4x16.
// ============================================================================
__global__ __launch_bounds__(256) void k2_gemm1(
    const float* __restrict__ W1, const float* __restrict__ b1)
{
    __shared__ float As[64*32];     // 8 KB
    __shared__ float Ws[32*256];    // 32 KB
    const int t  = threadIdx.x;
    const int r0 = blockIdx.x * 64;
    const int tr = t >> 4, tc = t & 15;

    float acc[4][16];
    #pragma unroll
    for (int r = 0; r < 4; r++)
        #pragma unroll
        for (int j = 0; j < 16; j++) acc[r][j] = 0.f;

    for (int k0 = 0; k0 < DD; k0 += 32) {
        #pragma unroll
        for (int p = 0; p < 8; p++) {
            const int i = t + 256*p;             // i = r*32 + c
            const int r = i >> 5, c = i & 31;
            As[i] = g_h0[(r0 + r)*DD + k0 + c];
        }
        #pragma unroll
        for (int p = 0; p < 32; p++) {
            const int i = t + 256*p;             // i = k*256 + col
            const int kk = i >> 8, c = i & 255;
            Ws[i] = W1[(k0 + kk)*D2 + c];
        }
        __syncthreads();

        #pragma unroll 8
        for (int k = 0; k < 32; k++) {
            float a[4];
            #pragma unroll
            for (int r = 0; r < 4; r++) a[r] = As[(tr*4 + r)*32 + k];
            const float4* wv = reinterpret_cast<const float4*>(Ws + k*256 + tc*16);
            float4 w0 = wv[0], w1 = wv[1], w2 = wv[2], w3 = wv[3];
            float w[16] = { w0.x,w0.y,w0.z,w0.w, w1.x,w1.y,w1.z,w1.w,
                            w2.x,w2.y,w2.z,w2.w, w3.x,w3.y,w3.z,w3.w };
            #pragma unroll
            for (int r = 0; r < 4; r++)
                #pragma unroll
                for (int j = 0; j < 16; j++)
                    acc[r][j] += a[r]*w[j];
        }
        __syncthreads();
    }

    float bv[16];
    #pragma unroll
    for (int j = 0; j < 16; j++) bv[j] = b1[tc*16 + j];
    #pragma unroll
    for (int r = 0; r < 4; r++) {
        const int row = r0 + tr*4 + r;
        #pragma unroll
        for (int j = 0; j < 16; j++)
            g_h1[row*D2 + tc*16 + j] = acc[r][j] + bv[j];
    }
}

// ============================================================================
// K2b: column sum / sumsq of h1. DETERMINISTIC: each block owns a fixed
// 256-row slab; fp32 partials to g_psum/g_psumsq (no atomics).
// 256 threads: thread t covers cols [(t&63)*4 .. +4) via float4, row
// parallelism via t>>6 (4 rows in flight).
// ============================================================================
__global__ __launch_bounds__(256) void k2b_stats()
{
    const int slab = blockIdx.x;                 // 0..511
    const int row0 = slab * (BN / NSTAT);        // 256 rows per slab
    const int c4   = threadIdx.x & 63;           // col group 0..63
    const int rpar = threadIdx.x >> 6;           // 0..3

    float4 s = make_float4(0.f,0.f,0.f,0.f);
    float4 q = make_float4(0.f,0.f,0.f,0.f);
    for (int r = rpar; r < BN/NSTAT; r += 4) {
        const float4 v = *reinterpret_cast<const float4*>(
            g_h1 + (size_t)(row0 + r)*D2 + c4*4);
        s.x += v.x; s.y += v.y; s.z += v.z; s.w += v.w;
        q.x += v.x*v.x; q.y += v.y*v.y; q.z += v.z*v.z; q.w += v.w*v.w;
    }

    // combine the 4 row-parallel partials per column group in smem (fixed order)
    __shared__ float4 sh_s[4][64];
    __shared__ float4 sh_q[4][64];
    sh_s[rpar][c4] = s;  sh_q[rpar][c4] = q;
    __syncthreads();
    if (rpar == 0) {
        float4 a = sh_s[0][c4], b = sh_s[1][c4], c = sh_s[2][c4], d = sh_s[3][c4];
        float4 e = sh_q[0][c4], f = sh_q[1][c4], gq = sh_q[2][c4], h = sh_q[3][c4];
        float4 S = make_float4(a.x+b.x+c.x+d.x, a.y+b.y+c.y+d.y,
                               a.z+b.z+c.z+d.z, a.w+b.w+c.w+d.w);
        float4 Q = make_float4(e.x+f.x+gq.x+h.x, e.y+f.y+gq.y+h.y,
                               e.z+f.z+gq.z+h.z, e.w+f.w+gq.w+h.w);
        *reinterpret_cast<float4*>(g_psum   + slab*D2 + c4*4) = S;
        *reinterpret_cast<float4*>(g_psumsq + slab*D2 + c4*4) = Q;
    }
}

// ============================================================================
// K3: finalize BN affine (scale/shift) + 1/||topk_w||. One block, 256 threads.
// Sequential fp64 sum over 512 partials -> bit-deterministic.
// ============================================================================
__global__ __launch_bounds__(256) void k3_finalize(
    const float* __restrict__ gamma, const float* __restrict__ beta,
    const float* __restrict__ tw)
{
    const int t = threadIdx.x;       // column
    double s = 0.0, q = 0.0;
    for (int b = 0; b < NSTAT; b++) {
        s += (double)g_psum[b*D2 + t];
        q += (double)g_psumsq[b*D2 + t];
    }
    const double mu  = s / (double)BN;
    double var = q / (double)BN - mu*mu;
    if (var < 0.0) var = 0.0;
    const double rs = 1.0 / sqrt(var + 1e-5);
    const double sc = (double)gamma[t] * rs;
    g_scale[t] = (float)sc;
    g_shift[t] = (float)((double)beta[t] - mu*sc);
    if (t == 0) {
        double nsum = 0.0;
        for (int i = 0; i < HH; i++) nsum += (double)tw[i]*(double)tw[i];
        g_invnorm = (float)(1.0 / sqrt(nsum));
    }
}

// ============================================================================
// K4: per-graph fused: BN+relu on h1, GEMM2 (64x256x256) -> h2 (smem only),
// projection scores, top-52 by rank, tanh gating, max/mean pool -> g_cat.
// Dynamic smem: union of [As 8KB | Ws 32KB] and h2s (64 x 257 floats).
// ============================================================================
__global__ __launch_bounds__(256) void k4_fused(
    const float* __restrict__ W2, const float* __restrict__ b2,
    const float* __restrict__ tw)
{
    extern __shared__ float sm[];
    float* As = sm;                 // 64*32
    float* Ws = sm + 2048;          // 32*256

    __shared__ float s_score[NN];
    __shared__ float s_gate[NN];
    __shared__ int   s_keep[NN];

    const int g = blockIdx.x;
    const int t = threadIdx.x;
    const int tr = t >> 4, tc = t & 15;
    const int r0 = g * NN;

    float acc[4][16];
    #pragma unroll
    for (int r = 0; r < 4; r++)
        #pragma unroll
        for (int j = 0; j < 16; j++) acc[r][j] = 0.f;

    for (int k0 = 0; k0 < D2; k0 += 32) {
        #pragma unroll
        for (int p = 0; p < 8; p++) {
            const int i = t + 256*p;
            const int r = i >> 5, c = i & 31;
            const int col = k0 + c;
            const float v = g_h1[(size_t)(r0 + r)*D2 + col];
            As[i] = fmaxf(v * g_scale[col] + g_shift[col], 0.f);
        }
        #pragma unroll
        for (int p = 0; p < 32; p++) {
            const int i = t + 256*p;
            const int kk = i >> 8, c = i & 255;
            Ws[i] = W2[(k0 + kk)*HH + c];
        }
        __syncthreads();

        #pragma unroll 8
        for (int k = 0; k < 32; k++) {
            float a[4];
            #pragma unroll
            for (int r = 0; r < 4; r++) a[r] = As[(tr*4 + r)*32 + k];
            const float4* wv = reinterpret_cast<const float4*>(Ws + k*256 + tc*16);
            float4 w0 = wv[0], w1 = wv[1], w2 = wv[2], w3 = wv[3];
            float w[16] = { w0.x,w0.y,w0.z,w0.w, w1.x,w1.y,w1.z,w1.w,
                            w2.x,w2.y,w2.z,w2.w, w3.x,w3.y,w3.z,w3.w };
            #pragma unroll
            for (int r = 0; r < 4; r++)
                #pragma unroll
                for (int j = 0; j < 16; j++)
                    acc[r][j] += a[r]*w[j];
        }
        __syncthreads();
    }

    // h2 (incl. bias) -> smem, pitch 257 (conflict-free column walks)
    float* h2s = sm;   // safe: last loop iter ended with __syncthreads()
    {
        float bv[16];
        #pragma unroll
        for (int j = 0; j < 16; j++) bv[j] = b2[tc*16 + j];
        #pragma unroll
        for (int r = 0; r < 4; r++)
            #pragma unroll
            for (int j = 0; j < 16; j++)
                h2s[(tr*4 + r)*257 + tc*16 + j] = acc[r][j] + bv[j];
    }
    __syncthreads();

    // projection scores: node n = t>>2, quarter q = t&3 over 64 cols, shfl-combine
    {
        const int n = t >> 2, q = t & 3;
        float p = 0.f;
        #pragma unroll 4
        for (int i = 0; i < 64; i++) {
            const int c = q*64 + i;
            p += h2s[n*257 + c] * tw[c];
        }
        p += __shfl_xor_sync(0xffffffffu, p, 1);
        p += __shfl_xor_sync(0xffffffffu, p, 2);
        if (q == 0) s_score[n] = p * g_invnorm;
    }
    __syncthreads();

    // top-52 by rank (ties: lower index wins, matching lax.top_k)
    if (t < NN) {
        const float si = s_score[t];
        int rank = 0;
        for (int j = 0; j < NN; j++) {
            const float sj = s_score[j];
            rank += (sj > si) || (sj == si && j < t);
        }
        s_keep[t] = (rank < KSEL);
        s_gate[t] = tanhf(si);
    }
    __syncthreads();

    // pooling: thread = column; uniform branch over nodes
    {
        float mx = -1e30f, sum = 0.f;
        for (int nn = 0; nn < NN; nn++) {
            if (s_keep[nn]) {
                const float v = h2s[nn*257 + t] * s_gate[nn];
                mx = fmaxf(mx, v);
                sum += v;
            }
        }
        g_cat[g*(2*HH) + t]      = mx;
        g_cat[g*(2*HH) + HH + t] = sum * (1.0f / (float)KSEL);
    }
}

// ============================================================================
// K5: out = cat @ fc_w^T + fc_b.   [2048 x 512] @ [512 x 256].
// Tile 64x64, K chunks of 64. grid (32, 4), 256 threads, thread tile 4x4.
// ============================================================================
__global__ __launch_bounds__(256) void k5_out(
    const float* __restrict__ fcw, const float* __restrict__ fcb,
    float* __restrict__ out)
{
    __shared__ float Asm[64*64];     // 16 KB (cat chunk)
    __shared__ float Wsm[64*65];     // 16.25 KB (fc_w chunk, transposed, padded)
    const int t  = threadIdx.x;
    const int b0 = blockIdx.x * 64;
    const int o0 = blockIdx.y * 64;
    const int tr = t >> 4, tc = t & 15;

    float acc[4][4];
    #pragma unroll
    for (int r = 0; r < 4; r++)
        #pragma unroll
        for (int j = 0; j < 4; j++) acc[r][j] = 0.f;

    for (int k0 = 0; k0 < 2*HH; k0 += 64) {
        #pragma unroll
        for (int p = 0; p < 16; p++) {
            const int i = t + 256*p;
            const int r = i >> 6, c = i & 63;
            Asm[i] = g_cat[(b0 + r)*(2*HH) + k0 + c];
        }
        #pragma unroll
        for (int p = 0; p < 16; p++) {
            const int i = t + 256*p;
            const int o = i >> 6, c = i & 63;
            Wsm[c*65 + o] = fcw[(o0 + o)*(2*HH) + k0 + c];
        }
        __syncthreads();

        #pragma unroll 8
        for (int k = 0; k < 64; k++) {
            float a[4], w[4];
            #pragma unroll
            for (int r = 0; r < 4; r++) a[r] = Asm[(tr*4 + r)*64 + k];
            #pragma unroll
            for (int j = 0; j < 4; j++) w[j] = Wsm[k*65 + tc*4 + j];
            #pragma unroll
            for (int r = 0; r < 4; r++)
                #pragma unroll
                for (int j = 0; j < 4; j++)
                    acc[r][j] += a[r]*w[j];
        }
        __syncthreads();
    }

    #pragma unroll
    for (int r = 0; r < 4; r++) {
        const int row = b0 + tr*4 + r;
        #pragma unroll
        for (int j = 0; j < 4; j++)
            out[row*HH + o0 + tc*4 + j] = acc[r][j] + fcb[o0 + tc*4 + j];
    }
}

// ============================================================================
extern "C" void kernel_launch(void* const* d_in, const int* in_sizes, int n_in,
                              void* d_out, int out_size)
{
    const int*   tokens = (const int*)  d_in[0];
    const int*   ntype  = (const int*)  d_in[1];
    const int*   eidx   = (const int*)  d_in[2];
    const float* st     = (const float*)d_in[3];
    const float* nt     = (const float*)d_in[4];
    const float* W1     = (const float*)d_in[5];
    const float* b1     = (const float*)d_in[6];
    const float* gamma  = (const float*)d_in[7];
    const float* beta   = (const float*)d_in[8];
    const float* W2     = (const float*)d_in[9];
    const float* b2     = (const float*)d_in[10];
    const float* tw     = (const float*)d_in[11];
    const float* fcw    = (const float*)d_in[12];
    const float* fcb    = (const float*)d_in[13];
    float* out = (float*)d_out;

    const int k4_smem = 64*257*4;   // 65792 B (union of GEMM stage + h2 buffer)
    cudaFuncSetAttribute(k4_fused, cudaFuncAttributeMaxDynamicSharedMemorySize,
                         k4_smem);

    k1_embed_edges<<<BB, 256>>>(tokens, ntype, eidx, st, nt);
    k2_gemm1<<<BN/64, 256>>>(W1, b1);
    k2b_stats<<<NSTAT, 256>>>();
    k3_finalize<<<1, 256>>>(gamma, beta, tw);
    k4_fused<<<BB, 256, k4_smem>>>(W2, b2, tw);
    k5_out<<<dim3(BB/64, HH/64), 256>>>(fcw, fcb, out);
}

// round 4
// speedup vs baseline: 1.0903x; 1.0903x over previous
#include <cuda_runtime.h>
#include <math.h>

// Problem constants
#define BB   2048                 // graphs
#define NN   64                   // nodes per graph
#define BN   (BB*NN)              // 131072 nodes
#define KSEL 52                   // top-k
#define TT   16                   // subtokens per node
#define DD   128                  // embed dim
#define D2   256                  // 2*D
#define HH   256                  // hidden
#define EPG  256                  // edges per graph
#define ETOT (BB*EPG)             // 524288 edges
#define NSTAT 512                 // stat-reduction blocks (BN/NSTAT = 256 rows each)

// ---------------- scratch (device globals; no allocation allowed) -----------
__device__ float  g_h0[BN*DD];          // 64 MB : x + agg  (GINE output pre-MLP)
__device__ float  g_h1[BN*D2];          // 128 MB: h0@W1 + b1 (pre-BN)
__device__ float  g_psum[NSTAT*D2];     // 512 KB: per-slab column sums
__device__ float  g_psumsq[NSTAT*D2];   // 512 KB
__device__ float  g_scale[D2];          // gamma * rsigma
__device__ float  g_shift[D2];          // beta - mu*gamma*rsigma
__device__ float  g_invnorm;            // 1/||topk_w||
__device__ float  g_cat[BB*2*HH];       // 4 MB : [max-pool || mean-pool]

// ---------------- packed f32x2 helpers (Blackwell FFMA2 path) ---------------
__device__ __forceinline__ unsigned long long pack_dup_f32(float a) {
    unsigned long long r;
    unsigned ai = __float_as_uint(a);
    asm("mov.b64 %0, {%1, %1};" : "=l"(r) : "r"(ai));
    return r;
}
__device__ __forceinline__ void ffma2(unsigned long long& d,
                                      unsigned long long a,
                                      unsigned long long b) {
    asm("fma.rn.f32x2 %0, %1, %2, %0;" : "+l"(d) : "l"(a), "l"(b));
}
__device__ __forceinline__ void unpack_f32x2(unsigned long long v,
                                             float& lo, float& hi) {
    unsigned l, h;
    asm("mov.b64 {%0, %1}, %2;" : "=r"(l), "=r"(h) : "l"(v));
    lo = __uint_as_float(l); hi = __uint_as_float(h);
}

// ============================================================================
// K1: per-graph block. subtoken-embed sum/avg + node-type embed -> x in smem;
// counting-sort edges by dst; agg = sum relu(x[src]); h0 = x + agg -> global.
// ============================================================================
__global__ __launch_bounds__(256) void k1_embed_edges(
    const int* __restrict__ tokens, const int* __restrict__ ntype,
    const int* __restrict__ eidx,
    const float* __restrict__ st, const float* __restrict__ nt)
{
    const int g = blockIdx.x;
    const int t = threadIdx.x;

    __shared__ int   s_tok[NN*TT];     // 4 KB
    __shared__ float s_inv[NN];
    __shared__ int   s_nt[NN];
    __shared__ float s_x[NN*DD];       // 32 KB
    __shared__ int   s_deg[NN];
    __shared__ int   s_start[NN+1];
    __shared__ int   s_src[EPG];

    if (t < NN) s_deg[t] = 0;
    #pragma unroll
    for (int p = 0; p < 4; p++) {
        int i = t + 256*p;
        s_tok[i] = tokens[g*(NN*TT) + i];
    }
    if (t < NN) s_nt[t] = ntype[g*NN + t];

    // edge endpoints (one edge per thread; edges stay within the graph)
    const int srcl = eidx[g*EPG + t]        - g*NN;
    const int dstl = eidx[ETOT + g*EPG + t] - g*NN;
    __syncthreads();

    // non-pad counts -> averaging factor (count==0 keeps raw sum)
    if (t < NN) {
        int c = 0;
        #pragma unroll
        for (int k = 0; k < TT; k++) c += (s_tok[t*TT + k] != 0);
        s_inv[t] = c ? (1.0f / (float)c) : 1.0f;
    }
    const int rank = atomicAdd(&s_deg[dstl], 1);
    __syncthreads();

    if (t == 0) {
        int a = 0;
        for (int n = 0; n < NN; n++) { s_start[n] = a; a += s_deg[n]; }
        s_start[NN] = a;
    }
    __syncthreads();
    s_src[s_start[dstl] + rank] = srcl;

    // x = avg(subtoken embeds) + node-type embed
    {
        const int d = t & 127;
        for (int n = (t >> 7); n < NN; n += 2) {
            float sum = 0.f;
            #pragma unroll
            for (int k = 0; k < TT; k++)
                sum += st[s_tok[n*TT + k]*DD + d];
            s_x[n*DD + d] = sum * s_inv[n] + nt[s_nt[n]*DD + d];
        }
    }
    __syncthreads();

    // aggregation: thread owns node n = t>>2, dim quarter q = t&3 (32 dims),
    // lane-staggered dim index -> conflict-free smem banks.
    const int n    = t >> 2;
    const int d0   = (t & 3) * 32;
    const int lane = t & 31;
    float acc[32];
    #pragma unroll
    for (int j = 0; j < 32; j++) acc[j] = 0.f;

    const int e0 = s_start[n], e1 = s_start[n+1];
    for (int e = e0; e < e1; e++) {
        const int s = s_src[e];
        #pragma unroll
        for (int j = 0; j < 32; j++) {
            const int dd = d0 + ((j + lane) & 31);
            acc[j] += fmaxf(s_x[s*DD + dd], 0.f);
        }
    }
    __syncthreads();   // all relu reads of s_x complete

    #pragma unroll
    for (int j = 0; j < 32; j++) {
        const int dd = d0 + ((j + lane) & 31);
        s_x[n*DD + dd] += acc[j];          // h0 = x + agg, unique (n,dd) owner
    }
    __syncthreads();

    // coalesced write-out
    #pragma unroll
    for (int p = 0; p < 32; p++) {
        const int i = t + 256*p;
        g_h0[g*(NN*DD) + i] = s_x[i];
    }
}

// ============================================================================
// K2: GEMM1  h1 = h0 @ W1 + b1.  Tile 64x256, K=128 in 32-chunks. 256 thr,
// thread tile 4 rows x 8 col-pairs, packed f32x2 accumulators (FFMA2).
// ============================================================================
__global__ __launch_bounds__(256) void k2_gemm1(
    const float* __restrict__ W1, const float* __restrict__ b1)
{
    __shared__ float As[64*32];     // 8 KB
    __shared__ float Ws[32*256];    // 32 KB
    const int t  = threadIdx.x;
    const int r0 = blockIdx.x * 64;
    const int tr = t >> 4, tc = t & 15;

    unsigned long long acc2[4][8];
    #pragma unroll
    for (int r = 0; r < 4; r++)
        #pragma unroll
        for (int p = 0; p < 8; p++) acc2[r][p] = 0ull;

    for (int k0 = 0; k0 < DD; k0 += 32) {
        #pragma unroll
        for (int p = 0; p < 8; p++) {
            const int i = t + 256*p;             // i = r*32 + c
            const int r = i >> 5, c = i & 31;
            As[i] = g_h0[(r0 + r)*DD + k0 + c];
        }
        #pragma unroll
        for (int p = 0; p < 32; p++) {
            const int i = t + 256*p;             // i = k*256 + col
            const int kk = i >> 8, c = i & 255;
            Ws[i] = W1[(k0 + kk)*D2 + c];
        }
        __syncthreads();

        #pragma unroll 8
        for (int k = 0; k < 32; k++) {
            unsigned long long aa[4];
            #pragma unroll
            for (int r = 0; r < 4; r++)
                aa[r] = pack_dup_f32(As[(tr*4 + r)*32 + k]);
            const ulonglong2* wp =
                reinterpret_cast<const ulonglong2*>(Ws + k*256 + tc*16);
            ulonglong2 wA = wp[0], wB = wp[1], wC = wp[2], wD = wp[3];
            unsigned long long w2[8] = { wA.x, wA.y, wB.x, wB.y,
                                         wC.x, wC.y, wD.x, wD.y };
            #pragma unroll
            for (int r = 0; r < 4; r++)
                #pragma unroll
                for (int p = 0; p < 8; p++)
                    ffma2(acc2[r][p], aa[r], w2[p]);
        }
        __syncthreads();
    }

    float bv[16];
    #pragma unroll
    for (int j = 0; j < 16; j++) bv[j] = b1[tc*16 + j];
    #pragma unroll
    for (int r = 0; r < 4; r++) {
        const int row = r0 + tr*4 + r;
        #pragma unroll
        for (int p = 0; p < 8; p++) {
            float lo, hi;
            unpack_f32x2(acc2[r][p], lo, hi);
            g_h1[(size_t)row*D2 + tc*16 + 2*p]     = lo + bv[2*p];
            g_h1[(size_t)row*D2 + tc*16 + 2*p + 1] = hi + bv[2*p + 1];
        }
    }
}

// ============================================================================
// K2b: column sum / sumsq of h1. DETERMINISTIC: each block owns a fixed
// 256-row slab; fp32 partials to g_psum/g_psumsq (no atomics).
// ============================================================================
__global__ __launch_bounds__(256) void k2b_stats()
{
    const int slab = blockIdx.x;                 // 0..511
    const int row0 = slab * (BN / NSTAT);        // 256 rows per slab
    const int c4   = threadIdx.x & 63;           // col group 0..63
    const int rpar = threadIdx.x >> 6;           // 0..3

    float4 s = make_float4(0.f,0.f,0.f,0.f);
    float4 q = make_float4(0.f,0.f,0.f,0.f);
    for (int r = rpar; r < BN/NSTAT; r += 4) {
        const float4 v = *reinterpret_cast<const float4*>(
            g_h1 + (size_t)(row0 + r)*D2 + c4*4);
        s.x += v.x; s.y += v.y; s.z += v.z; s.w += v.w;
        q.x += v.x*v.x; q.y += v.y*v.y; q.z += v.z*v.z; q.w += v.w*v.w;
    }

    __shared__ float4 sh_s[4][64];
    __shared__ float4 sh_q[4][64];
    sh_s[rpar][c4] = s;  sh_q[rpar][c4] = q;
    __syncthreads();
    if (rpar == 0) {
        float4 a = sh_s[0][c4], b = sh_s[1][c4], c = sh_s[2][c4], d = sh_s[3][c4];
        float4 e = sh_q[0][c4], f = sh_q[1][c4], gq = sh_q[2][c4], h = sh_q[3][c4];
        float4 S = make_float4(a.x+b.x+c.x+d.x, a.y+b.y+c.y+d.y,
                               a.z+b.z+c.z+d.z, a.w+b.w+c.w+d.w);
        float4 Q = make_float4(e.x+f.x+gq.x+h.x, e.y+f.y+gq.y+h.y,
                               e.z+f.z+gq.z+h.z, e.w+f.w+gq.w+h.w);
        *reinterpret_cast<float4*>(g_psum   + slab*D2 + c4*4) = S;
        *reinterpret_cast<float4*>(g_psumsq + slab*D2 + c4*4) = Q;
    }
}

// ============================================================================
// K3: finalize BN affine + 1/||topk_w||. PARALLEL: one block per column,
// 128 threads reduce the 512 partials (fp64 shfl tree, fixed order ->
// deterministic). Block 0 additionally reduces ||topk_w||^2.
// ============================================================================
__global__ __launch_bounds__(128) void k3_finalize(
    const float* __restrict__ gamma, const float* __restrict__ beta,
    const float* __restrict__ tw)
{
    const int col = blockIdx.x;     // 0..255
    const int t   = threadIdx.x;    // 0..127

    double s = 0.0, q = 0.0;
    #pragma unroll
    for (int b = t; b < NSTAT; b += 128) {
        s += (double)g_psum[b*D2 + col];
        q += (double)g_psumsq[b*D2 + col];
    }
    #pragma unroll
    for (int o = 16; o > 0; o >>= 1) {
        s += __shfl_down_sync(0xffffffffu, s, o);
        q += __shfl_down_sync(0xffffffffu, q, o);
    }
    __shared__ double ss[4], qq[4];
    if ((t & 31) == 0) { ss[t >> 5] = s; qq[t >> 5] = q; }
    __syncthreads();
    if (t == 0) {
        s = (ss[0] + ss[1]) + (ss[2] + ss[3]);
        q = (qq[0] + qq[1]) + (qq[2] + qq[3]);
        const double mu  = s / (double)BN;
        double var = q / (double)BN - mu*mu;
        if (var < 0.0) var = 0.0;
        const double rs = 1.0 / sqrt(var + 1e-5);
        const double sc = (double)gamma[col] * rs;
        g_scale[col] = (float)sc;
        g_shift[col] = (float)((double)beta[col] - mu*sc);
    }

    if (blockIdx.x == 0) {
        const double w0 = (double)tw[t];
        const double w1 = (double)tw[t + 128];
        double ns = w0*w0 + w1*w1;
        #pragma unroll
        for (int o = 16; o > 0; o >>= 1)
            ns += __shfl_down_sync(0xffffffffu, ns, o);
        __shared__ double sn[4];
        if ((t & 31) == 0) sn[t >> 5] = ns;
        __syncthreads();
        if (t == 0)
            g_invnorm = (float)(1.0 / sqrt((sn[0]+sn[1]) + (sn[2]+sn[3])));
    }
}

// ============================================================================
// K4: per-graph fused: BN+relu on h1, GEMM2 (64x256x256, f32x2) -> h2 (smem),
// projection scores, top-52 by rank, tanh gating, max/mean pool -> g_cat.
// ============================================================================
__global__ __launch_bounds__(256) void k4_fused(
    const float* __restrict__ W2, const float* __restrict__ b2,
    const float* __restrict__ tw)
{
    extern __shared__ float sm[];
    float* As = sm;                 // 64*32
    float* Ws = sm + 2048;          // 32*256

    __shared__ float s_score[NN];
    __shared__ float s_gate[NN];
    __shared__ int   s_keep[NN];

    const int g = blockIdx.x;
    const int t = threadIdx.x;
    const int tr = t >> 4, tc = t & 15;
    const int r0 = g * NN;

    unsigned long long acc2[4][8];
    #pragma unroll
    for (int r = 0; r < 4; r++)
        #pragma unroll
        for (int p = 0; p < 8; p++) acc2[r][p] = 0ull;

    for (int k0 = 0; k0 < D2; k0 += 32) {
        #pragma unroll
        for (int p = 0; p < 8; p++) {
            const int i = t + 256*p;
            const int r = i >> 5, c = i & 31;
            const int col = k0 + c;
            const float v = g_h1[(size_t)(r0 + r)*D2 + col];
            As[i] = fmaxf(v * g_scale[col] + g_shift[col], 0.f);
        }
        #pragma unroll
        for (int p = 0; p < 32; p++) {
            const int i = t + 256*p;
            const int kk = i >> 8, c = i & 255;
            Ws[i] = W2[(k0 + kk)*HH + c];
        }
        __syncthreads();

        #pragma unroll 8
        for (int k = 0; k < 32; k++) {
            unsigned long long aa[4];
            #pragma unroll
            for (int r = 0; r < 4; r++)
                aa[r] = pack_dup_f32(As[(tr*4 + r)*32 + k]);
            const ulonglong2* wp =
                reinterpret_cast<const ulonglong2*>(Ws + k*256 + tc*16);
            ulonglong2 wA = wp[0], wB = wp[1], wC = wp[2], wD = wp[3];
            unsigned long long w2[8] = { wA.x, wA.y, wB.x, wB.y,
                                         wC.x, wC.y, wD.x, wD.y };
            #pragma unroll
            for (int r = 0; r < 4; r++)
                #pragma unroll
                for (int p = 0; p < 8; p++)
                    ffma2(acc2[r][p], aa[r], w2[p]);
        }
        __syncthreads();
    }

    // h2 (incl. bias) -> smem, pitch 257 (conflict-free column walks)
    float* h2s = sm;   // safe: last loop iter ended with __syncthreads()
    {
        float bv[16];
        #pragma unroll
        for (int j = 0; j < 16; j++) bv[j] = b2[tc*16 + j];
        #pragma unroll
        for (int r = 0; r < 4; r++)
            #pragma unroll
            for (int p = 0; p < 8; p++) {
                float lo, hi;
                unpack_f32x2(acc2[r][p], lo, hi);
                h2s[(tr*4 + r)*257 + tc*16 + 2*p]     = lo + bv[2*p];
                h2s[(tr*4 + r)*257 + tc*16 + 2*p + 1] = hi + bv[2*p + 1];
            }
    }
    __syncthreads();

    // projection scores: node n = t>>2, quarter q = t&3 over 64 cols
    {
        const int n = t >> 2, q = t & 3;
        float p = 0.f;
        #pragma unroll 4
        for (int i = 0; i < 64; i++) {
            const int c = q*64 + i;
            p += h2s[n*257 + c] * tw[c];
        }
        p += __shfl_xor_sync(0xffffffffu, p, 1);
        p += __shfl_xor_sync(0xffffffffu, p, 2);
        if (q == 0) s_score[n] = p * g_invnorm;
    }
    __syncthreads();

    // top-52 by rank (ties: lower index wins, matching lax.top_k)
    if (t < NN) {
        const float si = s_score[t];
        int rank = 0;
        for (int j = 0; j < NN; j++) {
            const float sj = s_score[j];
            rank += (sj > si) || (sj == si && j < t);
        }
        s_keep[t] = (rank < KSEL);
        s_gate[t] = tanhf(si);
    }
    __syncthreads();

    // pooling: thread = column; uniform branch over nodes
    {
        float mx = -1e30f, sum = 0.f;
        for (int nn = 0; nn < NN; nn++) {
            if (s_keep[nn]) {
                const float v = h2s[nn*257 + t] * s_gate[nn];
                mx = fmaxf(mx, v);
                sum += v;
            }
        }
        g_cat[g*(2*HH) + t]      = mx;
        g_cat[g*(2*HH) + HH + t] = sum * (1.0f / (float)KSEL);
    }
}

// ============================================================================
// K5: out = cat @ fc_w^T + fc_b.   [2048 x 512] @ [512 x 256].
// ============================================================================
__global__ __launch_bounds__(256) void k5_out(
    const float* __restrict__ fcw, const float* __restrict__ fcb,
    float* __restrict__ out)
{
    __shared__ float Asm[64*64];     // 16 KB (cat chunk)
    __shared__ float Wsm[64*65];     // 16.25 KB (fc_w chunk, transposed, padded)
    const int t  = threadIdx.x;
    const int b0 = blockIdx.x * 64;
    const int o0 = blockIdx.y * 64;
    const int tr = t >> 4, tc = t & 15;

    float acc[4][4];
    #pragma unroll
    for (int r = 0; r < 4; r++)
        #pragma unroll
        for (int j = 0; j < 4; j++) acc[r][j] = 0.f;

    for (int k0 = 0; k0 < 2*HH; k0 += 64) {
        #pragma unroll
        for (int p = 0; p < 16; p++) {
            const int i = t + 256*p;
            const int r = i >> 6, c = i & 63;
            Asm[i] = g_cat[(b0 + r)*(2*HH) + k0 + c];
        }
        #pragma unroll
        for (int p = 0; p < 16; p++) {
            const int i = t + 256*p;
            const int o = i >> 6, c = i & 63;
            Wsm[c*65 + o] = fcw[(o0 + o)*(2*HH) + k0 + c];
        }
        __syncthreads();

        #pragma unroll 8
        for (int k = 0; k < 64; k++) {
            float a[4], w[4];
            #pragma unroll
            for (int r = 0; r < 4; r++) a[r] = Asm[(tr*4 + r)*64 + k];
            #pragma unroll
            for (int j = 0; j < 4; j++) w[j] = Wsm[k*65 + tc*4 + j];
            #pragma unroll
            for (int r = 0; r < 4; r++)
                #pragma unroll
                for (int j = 0; j < 4; j++)
                    acc[r][j] += a[r]*w[j];
        }
        __syncthreads();
    }

    #pragma unroll
    for (int r = 0; r < 4; r++) {
        const int row = b0 + tr*4 + r;
        #pragma unroll
        for (int j = 0; j < 4; j++)
            out[row*HH + o0 + tc*4 + j] = acc[r][j] + fcb[o0 + tc*4 + j];
    }
}

// ============================================================================
extern "C" void kernel_launch(void* const* d_in, const int* in_sizes, int n_in,
                              void* d_out, int out_size)
{
    const int*   tokens = (const int*)  d_in[0];
    const int*   ntype  = (const int*)  d_in[1];
    const int*   eidx   = (const int*)  d_in[2];
    const float* st     = (const float*)d_in[3];
    const float* nt     = (const float*)d_in[4];
    const float* W1     = (const float*)d_in[5];
    const float* b1     = (const float*)d_in[6];
    const float* gamma  = (const float*)d_in[7];
    const float* beta   = (const float*)d_in[8];
    const float* W2     = (const float*)d_in[9];
    const float* b2     = (const float*)d_in[10];
    const float* tw     = (const float*)d_in[11];
    const float* fcw    = (const float*)d_in[12];
    const float* fcb    = (const float*)d_in[13];
    float* out = (float*)d_out;

    const int k4_smem = 64*257*4;   // 65792 B (union of GEMM stage + h2 buffer)
    cudaFuncSetAttribute(k4_fused, cudaFuncAttributeMaxDynamicSharedMemorySize,
                         k4_smem);

    k1_embed_edges<<<BB, 256>>>(tokens, ntype, eidx, st, nt);
    k2_gemm1<<<BN/64, 256>>>(W1, b1);
    k2b_stats<<<NSTAT, 256>>>();
    k3_finalize<<<D2, 128>>>(gamma, beta, tw);
    k4_fused<<<BB, 256, k4_smem>>>(W2, b2, tw);
    k5_out<<<dim3(BB/64, HH/64), 256>>>(fcw, fcb, out);
}

// round 7
// speedup vs baseline: 3.3431x; 3.0662x over previous
#include <cuda_runtime.h>
#include <cuda_bf16.h>
#include <math.h>
#include <stdint.h>

// Problem constants
#define BB   2048                 // graphs
#define NN   64                   // nodes per graph
#define BN   (BB*NN)              // 131072 nodes
#define KSEL 52                   // top-k
#define TT   16                   // subtokens per node
#define DD   128                  // embed dim
#define D2   256                  // 2*D
#define HH   256                  // hidden
#define EPG  256                  // edges per graph
#define ETOT (BB*EPG)             // 524288 edges
#define NSTAT 512                 // BN stat slabs (256 rows each)

// ---------------- scratch (device globals; no allocation allowed) -----------
__device__ float    g_h1[BN*D2];           // 128 MB: h0@W1 + b1 (pre-BN)
__device__ uint32_t g_h0h[BN*DD/2];        // 16 MB : h0 hi bf16 pairs
__device__ uint32_t g_h0l[BN*DD/2];        // 16 MB : h0 lo bf16 pairs
__device__ uint32_t g_w1t_h[D2*DD/2];      // W1^T [n][k] hi bf16 pairs
__device__ uint32_t g_w1t_l[D2*DD/2];
__device__ uint32_t g_w2t_h[HH*D2/2];      // W2^T [n][k] hi bf16 pairs
__device__ uint32_t g_w2t_l[HH*D2/2];
__device__ float    g_psum[NSTAT*D2];
__device__ float    g_psumsq[NSTAT*D2];
__device__ float    g_scale[D2];
__device__ float    g_shift[D2];
__device__ float    g_invnorm;
__device__ float    g_cat[BB*2*HH];        // [max-pool || mean-pool]

// ---------------- helpers ----------------
__device__ __forceinline__ void split2(float x0, float x1, uint32_t& h, uint32_t& l) {
    __nv_bfloat162 hv, lv;
    hv.x = __float2bfloat16(x0); hv.y = __float2bfloat16(x1);
    lv.x = __float2bfloat16(x0 - __bfloat162float(hv.x));
    lv.y = __float2bfloat16(x1 - __bfloat162float(hv.y));
    h = *reinterpret_cast<uint32_t*>(&hv);
    l = *reinterpret_cast<uint32_t*>(&lv);
}
__device__ __forceinline__ uint32_t s2u(const void* p) {
    uint32_t a;
    asm("{ .reg .u64 t; cvta.to.shared.u64 t, %1; cvt.u32.u64 %0, t; }"
        : "=r"(a) : "l"(p));
    return a;
}
#define LDMX4(r0, r1, r2, r3, addr) \
    asm volatile("ldmatrix.sync.aligned.m8n8.x4.shared.b16 {%0,%1,%2,%3}, [%4];" \
                 : "=r"(r0), "=r"(r1), "=r"(r2), "=r"(r3) : "r"(addr))
#define LDMX2(r0, r1, addr) \
    asm volatile("ldmatrix.sync.aligned.m8n8.x2.shared.b16 {%0,%1}, [%2];" \
                 : "=r"(r0), "=r"(r1) : "r"(addr))
__device__ __forceinline__ void mma_bf16(float* c, const uint32_t* a,
                                         uint32_t b0, uint32_t b1) {
    asm volatile(
        "mma.sync.aligned.m16n8k16.row.col.f32.bf16.bf16.f32 "
        "{%0,%1,%2,%3}, {%4,%5,%6,%7}, {%8,%9}, {%0,%1,%2,%3};"
        : "+f"(c[0]), "+f"(c[1]), "+f"(c[2]), "+f"(c[3])
        : "r"(a[0]), "r"(a[1]), "r"(a[2]), "r"(a[3]), "r"(b0), "r"(b1));
}
// padded smem row stride for b16 tiles: 136 elements = 272 bytes (conflict-free)
#define RB 272

// ============================================================================
// K0: weight prep. Transpose W1/W2 to [n][k] and split to bf16 hi/lo pairs.
// grid 256 (n), 256 threads (k-pairs).
// ============================================================================
__global__ __launch_bounds__(256) void k0_prep(
    const float* __restrict__ W1, const float* __restrict__ W2)
{
    const int n = blockIdx.x;     // output row (transposed)
    const int t = threadIdx.x;
    if (t < D2/2) {               // W2: k pairs 0..127
        const float v0 = W2[(size_t)(2*t)  *HH + n];
        const float v1 = W2[(size_t)(2*t+1)*HH + n];
        uint32_t h, l; split2(v0, v1, h, l);
        g_w2t_h[n*(D2/2) + t] = h;
        g_w2t_l[n*(D2/2) + t] = l;
    }
    if (t < DD/2) {               // W1: k pairs 0..63
        const float v0 = W1[(size_t)(2*t)  *D2 + n];
        const float v1 = W1[(size_t)(2*t+1)*D2 + n];
        uint32_t h, l; split2(v0, v1, h, l);
        g_w1t_h[n*(DD/2) + t] = h;
        g_w1t_l[n*(DD/2) + t] = l;
    }
}

// ============================================================================
// K1: per-graph block. subtoken-embed sum/avg + node-type embed -> x in smem;
// counting-sort edges by dst; agg = sum relu(x[src]); h0 -> bf16 hi/lo global.
// ============================================================================
__global__ __launch_bounds__(256) void k1_embed_edges(
    const int* __restrict__ tokens, const int* __restrict__ ntype,
    const int* __restrict__ eidx,
    const float* __restrict__ st, const float* __restrict__ nt)
{
    const int g = blockIdx.x;
    const int t = threadIdx.x;

    __shared__ int   s_tok[NN*TT];
    __shared__ float s_inv[NN];
    __shared__ int   s_nt[NN];
    __shared__ float s_x[NN*DD];       // 32 KB
    __shared__ int   s_deg[NN];
    __shared__ int   s_start[NN+1];
    __shared__ int   s_src[EPG];

    if (t < NN) s_deg[t] = 0;
    #pragma unroll
    for (int p = 0; p < 4; p++) {
        int i = t + 256*p;
        s_tok[i] = tokens[g*(NN*TT) + i];
    }
    if (t < NN) s_nt[t] = ntype[g*NN + t];

    const int srcl = eidx[g*EPG + t]        - g*NN;
    const int dstl = eidx[ETOT + g*EPG + t] - g*NN;
    __syncthreads();

    if (t < NN) {
        int c = 0;
        #pragma unroll
        for (int k = 0; k < TT; k++) c += (s_tok[t*TT + k] != 0);
        s_inv[t] = c ? (1.0f / (float)c) : 1.0f;
    }
    const int rank = atomicAdd(&s_deg[dstl], 1);
    __syncthreads();

    if (t == 0) {
        int a = 0;
        for (int n = 0; n < NN; n++) { s_start[n] = a; a += s_deg[n]; }
        s_start[NN] = a;
    }
    __syncthreads();
    s_src[s_start[dstl] + rank] = srcl;

    // x = avg(subtoken embeds) + node-type embed  (float4 gathers)
    {
        const int c4 = t & 31;
        for (int n = (t >> 5); n < NN; n += 8) {
            float4 sum = make_float4(0.f,0.f,0.f,0.f);
            #pragma unroll
            for (int k = 0; k < TT; k++) {
                const float4 e = *reinterpret_cast<const float4*>(
                    st + (size_t)s_tok[n*TT + k]*DD + c4*4);
                sum.x += e.x; sum.y += e.y; sum.z += e.z; sum.w += e.w;
            }
            const float4 ne = *reinterpret_cast<const float4*>(
                nt + (size_t)s_nt[n]*DD + c4*4);
            const float iv = s_inv[n];
            float4 o;
            o.x = sum.x*iv + ne.x; o.y = sum.y*iv + ne.y;
            o.z = sum.z*iv + ne.z; o.w = sum.w*iv + ne.w;
            *reinterpret_cast<float4*>(&s_x[n*DD + c4*4]) = o;
        }
    }
    __syncthreads();

    // aggregation: node n = t>>2, dim quarter (t&3)*32, lane-staggered
    const int n    = t >> 2;
    const int d0   = (t & 3) * 32;
    const int lane = t & 31;
    float acc[32];
    #pragma unroll
    for (int j = 0; j < 32; j++) acc[j] = 0.f;

    const int e0 = s_start[n], e1 = s_start[n+1];
    for (int e = e0; e < e1; e++) {
        const int s = s_src[e];
        #pragma unroll
        for (int j = 0; j < 32; j++) {
            const int dd = d0 + ((j + lane) & 31);
            acc[j] += fmaxf(s_x[s*DD + dd], 0.f);
        }
    }
    __syncthreads();

    #pragma unroll
    for (int j = 0; j < 32; j++) {
        const int dd = d0 + ((j + lane) & 31);
        s_x[n*DD + dd] += acc[j];
    }
    __syncthreads();

    // write-out: bf16 hi/lo pairs (4096 pairs per graph)
    #pragma unroll
    for (int p = 0; p < 16; p++) {
        const int i = t + 256*p;
        uint32_t h, l; split2(s_x[2*i], s_x[2*i+1], h, l);
        g_h0h[(size_t)g*4096 + i] = h;
        g_h0l[(size_t)g*4096 + i] = l;
    }
}

// ============================================================================
// K2 (mma.sync): h1 = h0 @ W1 + b1.  Block tile 64(m) x 128(n), K=128 staged.
// 8 warps (2x4), warp tile 32x32. Split-bf16: AhBh + AlBh + AhBl.
// smem: Ah[64x136] Al Bh[128x136] Bl  = 104448 B dynamic.
// ============================================================================
#define K2_AH 0
#define K2_AL 17408
#define K2_BH 34816
#define K2_BL 69632
#define K2_SMEM 104448

__global__ __launch_bounds__(256) void k2_gemm1_mma(const float* __restrict__ b1)
{
    extern __shared__ char sb[];
    const int t = threadIdx.x, lane = t & 31, wid = t >> 5;
    const int r0 = blockIdx.x * 64;
    const int n0 = blockIdx.y * 128;
    const int wm = wid >> 2, wn = wid & 3;       // warp rows 32*wm, cols 32*wn
    const uint32_t sbase = s2u(sb);

    // stage A (64 x 128 bf16 pairs) and B (128 x 128)
    uint32_t* smu = reinterpret_cast<uint32_t*>(sb);
    #pragma unroll
    for (int p = 0; p < 16; p++) {
        const int i = t + 256*p;                 // 4096 pairs
        const int r = i >> 6, kp = i & 63;
        smu[(K2_AH>>2) + r*68 + kp] = g_h0h[(size_t)(r0 + r)*64 + kp];
        smu[(K2_AL>>2) + r*68 + kp] = g_h0l[(size_t)(r0 + r)*64 + kp];
        smu[(K2_BH>>2) + r*68 + kp] = g_w1t_h[(n0 + r)*64 + kp];   // r == n here
        smu[(K2_BL>>2) + r*68 + kp] = g_w1t_l[(n0 + r)*64 + kp];
        // second half of B rows (64..127)
        smu[(K2_BH>>2) + (r+64)*68 + kp] = g_w1t_h[(n0 + 64 + r)*64 + kp];
        smu[(K2_BL>>2) + (r+64)*68 + kp] = g_w1t_l[(n0 + 64 + r)*64 + kp];
    }
    __syncthreads();

    float acc[2][4][4];
    #pragma unroll
    for (int mt = 0; mt < 2; mt++)
        #pragma unroll
        for (int nt = 0; nt < 4; nt++)
            #pragma unroll
            for (int j = 0; j < 4; j++) acc[mt][nt][j] = 0.f;

    const uint32_t a_row = (uint32_t)(lane & 15);
    const uint32_t a_col = (uint32_t)((lane >> 4) * 8);
    const uint32_t b_row = (uint32_t)(lane & 7);
    const uint32_t b_col = (uint32_t)(((lane >> 3) & 1) * 8);

    #pragma unroll
    for (int ks = 0; ks < 8; ks++) {
        const uint32_t kb = (uint32_t)(ks * 16) * 2;
        uint32_t ah[2][4], al[2][4];
        #pragma unroll
        for (int mt = 0; mt < 2; mt++) {
            const uint32_t ad = sbase + K2_AH
                + (32*wm + mt*16 + a_row)*RB + kb + a_col*2;
            LDMX4(ah[mt][0], ah[mt][1], ah[mt][2], ah[mt][3], ad);
            LDMX4(al[mt][0], al[mt][1], al[mt][2], al[mt][3], ad + (K2_AL - K2_AH));
        }
        #pragma unroll
        for (int nt = 0; nt < 4; nt++) {
            const uint32_t bd = sbase + K2_BH
                + (wn*32 + nt*8 + b_row)*RB + kb + b_col*2;
            uint32_t bh0, bh1, bl0, bl1;
            LDMX2(bh0, bh1, bd);
            LDMX2(bl0, bl1, bd + (K2_BL - K2_BH));
            #pragma unroll
            for (int mt = 0; mt < 2; mt++) {
                mma_bf16(acc[mt][nt], ah[mt], bh0, bh1);
                mma_bf16(acc[mt][nt], al[mt], bh0, bh1);
                mma_bf16(acc[mt][nt], ah[mt], bl0, bl1);
            }
        }
    }

    // epilogue: bias + direct fragment stores to g_h1
    const int gq = lane >> 2, tig = lane & 3;
    #pragma unroll
    for (int mt = 0; mt < 2; mt++) {
        const int row = r0 + 32*wm + mt*16 + gq;
        #pragma unroll
        for (int nt = 0; nt < 4; nt++) {
            const int col = n0 + wn*32 + nt*8 + tig*2;
            const float bb0 = b1[col], bb1 = b1[col+1];
            float2 v0 = make_float2(acc[mt][nt][0] + bb0, acc[mt][nt][1] + bb1);
            float2 v1 = make_float2(acc[mt][nt][2] + bb0, acc[mt][nt][3] + bb1);
            *reinterpret_cast<float2*>(g_h1 + (size_t)row*D2 + col)     = v0;
            *reinterpret_cast<float2*>(g_h1 + (size_t)(row+8)*D2 + col) = v1;
        }
    }
}

// ============================================================================
// K2b: column sum / sumsq of h1. Deterministic slab partials.
// ============================================================================
__global__ __launch_bounds__(256) void k2b_stats()
{
    const int slab = blockIdx.x;
    const int row0 = slab * (BN / NSTAT);
    const int c4   = threadIdx.x & 63;
    const int rpar = threadIdx.x >> 6;

    float4 s = make_float4(0.f,0.f,0.f,0.f);
    float4 q = make_float4(0.f,0.f,0.f,0.f);
    for (int r = rpar; r < BN/NSTAT; r += 4) {
        const float4 v = *reinterpret_cast<const float4*>(
            g_h1 + (size_t)(row0 + r)*D2 + c4*4);
        s.x += v.x; s.y += v.y; s.z += v.z; s.w += v.w;
        q.x += v.x*v.x; q.y += v.y*v.y; q.z += v.z*v.z; q.w += v.w*v.w;
    }
    __shared__ float4 sh_s[4][64];
    __shared__ float4 sh_q[4][64];
    sh_s[rpar][c4] = s;  sh_q[rpar][c4] = q;
    __syncthreads();
    if (rpar == 0) {
        float4 a = sh_s[0][c4], b = sh_s[1][c4], c = sh_s[2][c4], d = sh_s[3][c4];
        float4 e = sh_q[0][c4], f = sh_q[1][c4], gq = sh_q[2][c4], h = sh_q[3][c4];
        float4 S = make_float4(a.x+b.x+c.x+d.x, a.y+b.y+c.y+d.y,
                               a.z+b.z+c.z+d.z, a.w+b.w+c.w+d.w);
        float4 Q = make_float4(e.x+f.x+gq.x+h.x, e.y+f.y+gq.y+h.y,
                               e.z+f.z+gq.z+h.z, e.w+f.w+gq.w+h.w);
        *reinterpret_cast<float4*>(g_psum   + slab*D2 + c4*4) = S;
        *reinterpret_cast<float4*>(g_psumsq + slab*D2 + c4*4) = Q;
    }
}

// ============================================================================
// K3: finalize BN affine + 1/||topk_w||. One block per column.
// ============================================================================
__global__ __launch_bounds__(128) void k3_finalize(
    const float* __restrict__ gamma, const float* __restrict__ beta,
    const float* __restrict__ tw)
{
    const int col = blockIdx.x;
    const int t   = threadIdx.x;

    double s = 0.0, q = 0.0;
    #pragma unroll
    for (int b = t; b < NSTAT; b += 128) {
        s += (double)g_psum[b*D2 + col];
        q += (double)g_psumsq[b*D2 + col];
    }
    #pragma unroll
    for (int o = 16; o > 0; o >>= 1) {
        s += __shfl_down_sync(0xffffffffu, s, o);
        q += __shfl_down_sync(0xffffffffu, q, o);
    }
    __shared__ double ss[4], qq[4];
    if ((t & 31) == 0) { ss[t >> 5] = s; qq[t >> 5] = q; }
    __syncthreads();
    if (t == 0) {
        s = (ss[0] + ss[1]) + (ss[2] + ss[3]);
        q = (qq[0] + qq[1]) + (qq[2] + qq[3]);
        const double mu  = s / (double)BN;
        double var = q / (double)BN - mu*mu;
        if (var < 0.0) var = 0.0;
        const double rs = 1.0 / sqrt(var + 1e-5);
        const double sc = (double)gamma[col] * rs;
        g_scale[col] = (float)sc;
        g_shift[col] = (float)((double)beta[col] - mu*sc);
    }
    if (blockIdx.x == 0) {
        const double w0 = (double)tw[t];
        const double w1 = (double)tw[t + 128];
        double ns = w0*w0 + w1*w1;
        #pragma unroll
        for (int o = 16; o > 0; o >>= 1)
            ns += __shfl_down_sync(0xffffffffu, ns, o);
        __shared__ double sn[4];
        if ((t & 31) == 0) sn[t >> 5] = ns;
        __syncthreads();
        if (t == 0)
            g_invnorm = (float)(1.0 / sqrt((sn[0]+sn[1]) + (sn[2]+sn[3])));
    }
}

// ============================================================================
// K4 (mma.sync, fused): per graph: BN+relu(h1) @ W2 + b2 -> h2 (smem) -> score
// -> top-52 -> tanh gate -> max/mean pool -> g_cat.
// 8 warps (2x4), warp tile 32x64, K=256 in 2 staged chunks of 128.
// smem: Ah[64x136] Al Bh[256x136] Bl = 174080 B dynamic; h2 tile reuses it.
// ============================================================================
#define K4_AH 0
#define K4_AL 17408
#define K4_BH 34816
#define K4_BL 104448
#define K4_SMEM 174080

__global__ __launch_bounds__(256) void k4_fused_mma(
    const float* __restrict__ b2, const float* __restrict__ tw)
{
    extern __shared__ char sb[];
    __shared__ float s_sc[D2], s_sh[D2], s_b2[HH];
    __shared__ float s_score[NN], s_gate[NN];
    __shared__ int   s_keep[NN];

    const int g = blockIdx.x;
    const int t = threadIdx.x, lane = t & 31, wid = t >> 5;
    const int r0 = g * NN;
    const int wm = wid >> 2, wn = wid & 3;       // warp rows 32*wm, cols 64*wn
    const uint32_t sbase = s2u(sb);

    s_sc[t] = g_scale[t];
    s_sh[t] = g_shift[t];
    s_b2[t] = b2[t];
    __syncthreads();

    float acc[2][8][4];
    #pragma unroll
    for (int mt = 0; mt < 2; mt++)
        #pragma unroll
        for (int nt = 0; nt < 8; nt++)
            #pragma unroll
            for (int j = 0; j < 4; j++) acc[mt][nt][j] = 0.f;

    uint32_t* smu = reinterpret_cast<uint32_t*>(sb);
    const uint32_t a_row = (uint32_t)(lane & 15);
    const uint32_t a_col = (uint32_t)((lane >> 4) * 8);
    const uint32_t b_row = (uint32_t)(lane & 7);
    const uint32_t b_col = (uint32_t)(((lane >> 3) & 1) * 8);

    for (int kc = 0; kc < 2; kc++) {
        const int kbase = kc * 128;
        // stage A: BN+relu on the fly, split bf16 (4096 pairs)
        #pragma unroll
        for (int p = 0; p < 16; p++) {
            const int i = t + 256*p;
            const int r = i >> 6, kp = i & 63;
            const int col = kbase + kp*2;
            const float2 v = *reinterpret_cast<const float2*>(
                g_h1 + (size_t)(r0 + r)*D2 + col);
            const float x0 = fmaxf(v.x * s_sc[col]   + s_sh[col],   0.f);
            const float x1 = fmaxf(v.y * s_sc[col+1] + s_sh[col+1], 0.f);
            uint32_t h, l; split2(x0, x1, h, l);
            smu[(K4_AH>>2) + r*68 + kp] = h;
            smu[(K4_AL>>2) + r*68 + kp] = l;
        }
        // stage B: 256 n-rows x 64 k-pairs from prepped W2^T
        #pragma unroll 8
        for (int p = 0; p < 64; p++) {
            const int i = t + 256*p;                 // 16384 u32
            const int n = i >> 6, kp = i & 63;
            smu[(K4_BH>>2) + n*68 + kp] = g_w2t_h[n*128 + kc*64 + kp];
            smu[(K4_BL>>2) + n*68 + kp] = g_w2t_l[n*128 + kc*64 + kp];
        }
        __syncthreads();

        #pragma unroll
        for (int ks = 0; ks < 8; ks++) {
            const uint32_t kb = (uint32_t)(ks * 16) * 2;
            uint32_t ah[2][4], al[2][4];
            #pragma unroll
            for (int mt = 0; mt < 2; mt++) {
                const uint32_t ad = sbase + K4_AH
                    + (32*wm + mt*16 + a_row)*RB + kb + a_col*2;
                LDMX4(ah[mt][0], ah[mt][1], ah[mt][2], ah[mt][3], ad);
                LDMX4(al[mt][0], al[mt][1], al[mt][2], al[mt][3],
                      ad + (K4_AL - K4_AH));
            }
            #pragma unroll
            for (int nt = 0; nt < 8; nt++) {
                const uint32_t bd = sbase + K4_BH
                    + (wn*64 + nt*8 + b_row)*RB + kb + b_col*2;
                uint32_t bh0, bh1, bl0, bl1;
                LDMX2(bh0, bh1, bd);
                LDMX2(bl0, bl1, bd + (K4_BL - K4_BH));
                #pragma unroll
                for (int mt = 0; mt < 2; mt++) {
                    mma_bf16(acc[mt][nt], ah[mt], bh0, bh1);
                    mma_bf16(acc[mt][nt], al[mt], bh0, bh1);
                    mma_bf16(acc[mt][nt], ah[mt], bl0, bl1);
                }
            }
        }
        __syncthreads();    // before next chunk restages smem
    }

    // h2 tile (pitch 260 f32) into smem (reuses staging region)
    float* h2s = reinterpret_cast<float*>(sb);
    {
        const int gq = lane >> 2, tig = lane & 3;
        #pragma unroll
        for (int mt = 0; mt < 2; mt++) {
            const int row = 32*wm + mt*16 + gq;
            #pragma unroll
            for (int nt = 0; nt < 8; nt++) {
                const int col = wn*64 + nt*8 + tig*2;
                h2s[row*260 + col]       = acc[mt][nt][0] + s_b2[col];
                h2s[row*260 + col + 1]   = acc[mt][nt][1] + s_b2[col+1];
                h2s[(row+8)*260 + col]   = acc[mt][nt][2] + s_b2[col];
                h2s[(row+8)*260 + col+1] = acc[mt][nt][3] + s_b2[col+1];
            }
        }
    }
    __syncthreads();

    // projection scores: node n = t>>2, quarter q = t&3, staggered cols
    {
        const int n = t >> 2, q = t & 3;
        float p = 0.f;
        #pragma unroll 4
        for (int i = 0; i < 64; i++) {
            const int c = q*64 + ((i + q*16) & 63);
            p += h2s[n*260 + c] * tw[c];
        }
        p += __shfl_xor_sync(0xffffffffu, p, 1);
        p += __shfl_xor_sync(0xffffffffu, p, 2);
        if (q == 0) s_score[n] = p * g_invnorm;
    }
    __syncthreads();

    // top-52 by rank (ties: lower index wins)
    if (t < NN) {
        const float si = s_score[t];
        int rank = 0;
        for (int j = 0; j < NN; j++) {
            const float sj = s_score[j];
            rank += (sj > si) || (sj == si && j < t);
        }
        s_keep[t] = (rank < KSEL);
        s_gate[t] = tanhf(si);
    }
    __syncthreads();

    // pooling: thread = column
    {
        float mx = -1e30f, sum = 0.f;
        for (int nn = 0; nn < NN; nn++) {
            if (s_keep[nn]) {
                const float v = h2s[nn*260 + t] * s_gate[nn];
                mx = fmaxf(mx, v);
                sum += v;
            }
        }
        g_cat[g*(2*HH) + t]      = mx;
        g_cat[g*(2*HH) + HH + t] = sum * (1.0f / (float)KSEL);
    }
}

// ============================================================================
// K5: out = cat @ fc_w^T + fc_b.   [2048 x 512] @ [512 x 256].
// ============================================================================
__global__ __launch_bounds__(256) void k5_out(
    const float* __restrict__ fcw, const float* __restrict__ fcb,
    float* __restrict__ out)
{
    __shared__ float Asm[64*64];
    __shared__ float Wsm[64*65];
    const int t  = threadIdx.x;
    const int b0 = blockIdx.x * 64;
    const int o0 = blockIdx.y * 64;
    const int tr = t >> 4, tc = t & 15;

    float acc[4][4];
    #pragma unroll
    for (int r = 0; r < 4; r++)
        #pragma unroll
        for (int j = 0; j < 4; j++) acc[r][j] = 0.f;

    for (int k0 = 0; k0 < 2*HH; k0 += 64) {
        #pragma unroll
        for (int p = 0; p < 16; p++) {
            const int i = t + 256*p;
            const int r = i >> 6, c = i & 63;
            Asm[i] = g_cat[(b0 + r)*(2*HH) + k0 + c];
        }
        #pragma unroll
        for (int p = 0; p < 16; p++) {
            const int i = t + 256*p;
            const int o = i >> 6, c = i & 63;
            Wsm[c*65 + o] = fcw[(o0 + o)*(2*HH) + k0 + c];
        }
        __syncthreads();

        #pragma unroll 8
        for (int k = 0; k < 64; k++) {
            float a[4], w[4];
            #pragma unroll
            for (int r = 0; r < 4; r++) a[r] = Asm[(tr*4 + r)*64 + k];
            #pragma unroll
            for (int j = 0; j < 4; j++) w[j] = Wsm[k*65 + tc*4 + j];
            #pragma unroll
            for (int r = 0; r < 4; r++)
                #pragma unroll
                for (int j = 0; j < 4; j++)
                    acc[r][j] += a[r]*w[j];
        }
        __syncthreads();
    }

    #pragma unroll
    for (int r = 0; r < 4; r++) {
        const int row = b0 + tr*4 + r;
        #pragma unroll
        for (int j = 0; j < 4; j++)
            out[row*HH + o0 + tc*4 + j] = acc[r][j] + fcb[o0 + tc*4 + j];
    }
}

// ============================================================================
extern "C" void kernel_launch(void* const* d_in, const int* in_sizes, int n_in,
                              void* d_out, int out_size)
{
    const int*   tokens = (const int*)  d_in[0];
    const int*   ntype  = (const int*)  d_in[1];
    const int*   eidx   = (const int*)  d_in[2];
    const float* st     = (const float*)d_in[3];
    const float* nt     = (const float*)d_in[4];
    const float* W1     = (const float*)d_in[5];
    const float* b1     = (const float*)d_in[6];
    const float* gamma  = (const float*)d_in[7];
    const float* beta   = (const float*)d_in[8];
    const float* W2     = (const float*)d_in[9];
    const float* b2     = (const float*)d_in[10];
    const float* tw     = (const float*)d_in[11];
    const float* fcw    = (const float*)d_in[12];
    const float* fcb    = (const float*)d_in[13];
    float* out = (float*)d_out;

    cudaFuncSetAttribute(k2_gemm1_mma, cudaFuncAttributeMaxDynamicSharedMemorySize,
                         K2_SMEM);
    cudaFuncSetAttribute(k4_fused_mma, cudaFuncAttributeMaxDynamicSharedMemorySize,
                         K4_SMEM);

    k0_prep<<<D2, 256>>>(W1, W2);
    k1_embed_edges<<<BB, 256>>>(tokens, ntype, eidx, st, nt);
    k2_gemm1_mma<<<dim3(BN/64, 2), 256, K2_SMEM>>>(b1);
    k2b_stats<<<NSTAT, 256>>>();
    k3_finalize<<<D2, 128>>>(gamma, beta, tw);
    k4_fused_mma<<<BB, 256, K4_SMEM>>>(b2, tw);
    k5_out<<<dim3(BB/64, HH/64), 256>>>(fcw, fcb, out);
}